// round 1
// baseline (speedup 1.0000x reference)
#include <cuda_runtime.h>

#define HH 128
#define WW 128
#define CC 16
#define NPIX (HH*WW)
#define NRES 5
#define NLINES (NRES*NPIX)
#define NPTS 32
#define SCALE 5.0f
#define LOI_ELEMS (NLINES*CC*NPTS)

// scratch (no allocations allowed)
__device__ float g_lines[NLINES*4];      // 1.31 MB  (x_st,y_st,x_ed,y_ed)
__device__ float g_tfeat[NPIX*CC];       // 1 MB, channel-last transposed features
__device__ float g_cand_v[NPIX];
__device__ int   g_cand_i[NPIX];
__device__ int   g_zero_i[NPIX];
__device__ int   g_cnt[2];

__global__ void k_reset() { g_cnt[0] = 0; g_cnt[1] = 0; }

__global__ void k_prep(const float* __restrict__ md, const float* __restrict__ dis,
                       const float* __restrict__ res, const float* __restrict__ feat,
                       const float* __restrict__ jloc)
{
    int idx = blockIdx.x * blockDim.x + threadIdx.x;
    if (idx >= NPIX) return;
    int x = idx & (WW-1), y = idx >> 7;

    // --- transpose features to [y][x][c] (channel-last) ---
    #pragma unroll
    for (int c = 0; c < CC; ++c)
        g_tfeat[idx*CC + c] = feat[c*NPIX + idx];

    // --- hafm decoding: per-pixel trig hoisted over 5 residuals ---
    const float PI = 3.14159265358979323846f;
    float md0 = md[idx], md1 = md[NPIX+idx], md2 = md[2*NPIX+idx];
    float md_un = (md0 - 0.5f) * (2.0f * PI);
    float cs  = cosf(md_un);
    float ss  = sinf(md_un);
    float yst = tanf(md1 * (PI * 0.5f));
    float yed = tanf(-md2 * (PI * 0.5f));
    float d0 = dis[idx], r0 = res[idx];
    float ax_st = cs - ss*yst, ay_st = ss + cs*yst;
    float ax_ed = cs - ss*yed, ay_ed = ss + cs*yed;
    float fx = (float)x, fy = (float)y;
    #pragma unroll
    for (int r = 0; r < NRES; ++r) {
        float sign = (float)(r - 2);
        float dist = fminf(fmaxf(d0 + r0*sign, 0.0f), 1.0f) * SCALE;
        float4 L;
        L.x = fminf(fmaxf(ax_st*dist + fx, 0.0f), (float)(WW-1));
        L.y = fminf(fmaxf(ay_st*dist + fy, 0.0f), (float)(HH-1));
        L.z = fminf(fmaxf(ax_ed*dist + fx, 0.0f), (float)(WW-1));
        L.w = fminf(fmaxf(ay_ed*dist + fy, 0.0f), (float)(HH-1));
        ((float4*)g_lines)[r*NPIX + idx] = L;
    }

    // --- 3x3 NMS on jloc + compaction of candidates ---
    float a = jloc[idx];
    float m = -1e30f;
    #pragma unroll
    for (int dy = -1; dy <= 1; ++dy) {
        int yy = y + dy;
        if (yy < 0 || yy >= HH) continue;
        #pragma unroll
        for (int dx = -1; dx <= 1; ++dx) {
            int xx = x + dx;
            if (xx < 0 || xx >= WW) continue;
            m = fmaxf(m, jloc[yy*WW + xx]);
        }
    }
    float v = (a == m) ? a : 0.0f;
    if (v > 0.0f) {
        int p = atomicAdd(&g_cnt[0], 1);
        g_cand_v[p] = v;
        g_cand_i[p] = idx;
    } else {
        int p = atomicAdd(&g_cnt[1], 1);
        g_zero_i[p] = idx;
    }
}

// One warp per line, one lane per t-point, 16 channels per thread.
__global__ void __launch_bounds__(256) k_loi(float* __restrict__ out)
{
    int lane = threadIdx.x & 31;
    int line = (blockIdx.x * blockDim.x + threadIdx.x) >> 5;

    float4 L = ((const float4*)g_lines)[line];   // warp-broadcast
    float tf = (float)lane * (1.0f / 31.0f);     // tspan = linspace(0,1,32)
    // pts = U*t + V*(1-t) - 0.5, U = (x_st,y_st), V = (x_ed,y_ed)
    float px = L.x*tf + L.z*(1.0f - tf) - 0.5f;
    float py = L.y*tf + L.w*(1.0f - tf) - 0.5f;

    float px0 = fminf(fmaxf(floorf(px), 0.0f), (float)(WW-1));
    float py0 = fminf(fmaxf(floorf(py), 0.0f), (float)(HH-1));
    float px1 = fminf(px0 + 1.0f, (float)(WW-1));
    float py1 = fminf(py0 + 1.0f, (float)(HH-1));
    float wx0 = px1 - px, wx1 = px - px0;
    float wy0 = py1 - py, wy1 = py - py0;
    float w00 = wy0*wx0, w10 = wy1*wx0, w01 = wy0*wx1, w11 = wy1*wx1;
    int ix0 = (int)px0, iy0 = (int)py0, ix1 = (int)px1, iy1 = (int)py1;

    const float4* f00 = (const float4*)&g_tfeat[(iy0*WW + ix0)*CC];
    const float4* f10 = (const float4*)&g_tfeat[(iy1*WW + ix0)*CC];
    const float4* f01 = (const float4*)&g_tfeat[(iy0*WW + ix1)*CC];
    const float4* f11 = (const float4*)&g_tfeat[(iy1*WW + ix1)*CC];

    float acc[CC];
    #pragma unroll
    for (int q = 0; q < 4; ++q) {
        float4 a = f00[q], b = f10[q], c = f01[q], d = f11[q];
        acc[4*q+0] = a.x*w00 + b.x*w10 + c.x*w01 + d.x*w11;
        acc[4*q+1] = a.y*w00 + b.y*w10 + c.y*w01 + d.y*w11;
        acc[4*q+2] = a.z*w00 + b.z*w10 + c.z*w01 + d.z*w11;
        acc[4*q+3] = a.w*w00 + b.w*w10 + c.w*w01 + d.w*w11;
    }

    // loi[line][c*32 + t]; per-c store is 128B coalesced across the warp
    float* row = out + (size_t)line * (CC*NPTS) + lane;
    #pragma unroll
    for (int c = 0; c < CC; ++c) row[c*NPTS] = acc[c];
}

// Single block; rank-by-count selection (matches jax.lax.top_k stable order).
__global__ void k_topk(const float* __restrict__ joff, const int* __restrict__ topk,
                       float* __restrict__ out)
{
    int K = topk[0];
    int M = g_cnt[0];
    float* junc = out + (size_t)LOI_ELEMS;
    float* sc   = junc + 2*(size_t)K;

    for (int i = threadIdx.x; i < M; i += blockDim.x) {
        float v = g_cand_v[i];
        int  id = g_cand_i[i];
        int rank = 0;
        for (int j = 0; j < M; ++j) {
            float vj = g_cand_v[j];
            rank += (vj > v) || (vj == v && g_cand_i[j] < id);
        }
        if (rank < K) {
            sc[rank] = v;
            junc[2*rank+0] = (float)(id & (WW-1)) + joff[id]        + 0.5f;
            junc[2*rank+1] = (float)(id >> 7)     + joff[NPIX + id] + 0.5f;
        }
    }

    // fallback: fewer positive maxima than K -> fill with zeros in index order
    if (M < K) {
        int Z = g_cnt[1];
        for (int i = threadIdx.x; i < Z; i += blockDim.x) {
            int id = g_zero_i[i];
            int zr = 0;
            for (int j = 0; j < Z; ++j) zr += (g_zero_i[j] < id);
            int rank = M + zr;
            if (rank < K) {
                sc[rank] = 0.0f;
                junc[2*rank+0] = (float)(id & (WW-1)) + joff[id]        + 0.5f;
                junc[2*rank+1] = (float)(id >> 7)     + joff[NPIX + id] + 0.5f;
            }
        }
    }
}

extern "C" void kernel_launch(void* const* d_in, const int* in_sizes, int n_in,
                              void* d_out, int out_size)
{
    const float* md   = (const float*)d_in[0];
    const float* dis  = (const float*)d_in[1];
    const float* res  = (const float*)d_in[2];
    const float* feat = (const float*)d_in[3];
    const float* jloc = (const float*)d_in[4];
    const float* joff = (const float*)d_in[5];
    const int*   topk = (const int*)d_in[6];
    float* out = (float*)d_out;

    k_reset<<<1, 1>>>();
    k_prep<<<NPIX/256, 256>>>(md, dis, res, feat, jloc);
    k_loi<<<NLINES/8, 256>>>(out);          // 10240 blocks x 8 warps, 1 line/warp
    k_topk<<<1, 512>>>(joff, topk, out);
}

// round 2
// speedup vs baseline: 3.2049x; 3.2049x over previous
#include <cuda_runtime.h>

#define HH 128
#define WW 128
#define CC 16
#define NPIX (HH*WW)
#define NRES 5
#define NLINES (NRES*NPIX)
#define NPTS 32
#define SCALE 5.0f
#define LOI_ELEMS (NLINES*CC*NPTS)
#define TTILE 2048

// scratch (no allocations allowed)
__device__ float g_lines[NLINES*4];      // 1.31 MB  (x_st,y_st,x_ed,y_ed)
__device__ float g_tfeat[NPIX*CC];       // 1 MB, channel-last transposed features
__device__ float g_cand_v[NPIX];
__device__ int   g_cand_i[NPIX];
__device__ int   g_zero_i[NPIX];
__device__ int   g_cnt[2];

__global__ void k_reset() { g_cnt[0] = 0; g_cnt[1] = 0; }

__global__ void k_prep(const float* __restrict__ md, const float* __restrict__ dis,
                       const float* __restrict__ res, const float* __restrict__ feat,
                       const float* __restrict__ jloc)
{
    int idx = blockIdx.x * blockDim.x + threadIdx.x;
    if (idx >= NPIX) return;
    int x = idx & (WW-1), y = idx >> 7;

    // --- transpose features to [y][x][c] (channel-last) ---
    #pragma unroll
    for (int c = 0; c < CC; ++c)
        g_tfeat[idx*CC + c] = feat[c*NPIX + idx];

    // --- hafm decoding: per-pixel trig hoisted over 5 residuals ---
    const float PI = 3.14159265358979323846f;
    float md0 = md[idx], md1 = md[NPIX+idx], md2 = md[2*NPIX+idx];
    float md_un = (md0 - 0.5f) * (2.0f * PI);
    float cs  = cosf(md_un);
    float ss  = sinf(md_un);
    float yst = tanf(md1 * (PI * 0.5f));
    float yed = tanf(-md2 * (PI * 0.5f));
    float d0 = dis[idx], r0 = res[idx];
    float ax_st = cs - ss*yst, ay_st = ss + cs*yst;
    float ax_ed = cs - ss*yed, ay_ed = ss + cs*yed;
    float fx = (float)x, fy = (float)y;
    #pragma unroll
    for (int r = 0; r < NRES; ++r) {
        float sign = (float)(r - 2);
        float dist = fminf(fmaxf(d0 + r0*sign, 0.0f), 1.0f) * SCALE;
        float4 L;
        L.x = fminf(fmaxf(ax_st*dist + fx, 0.0f), (float)(WW-1));
        L.y = fminf(fmaxf(ay_st*dist + fy, 0.0f), (float)(HH-1));
        L.z = fminf(fmaxf(ax_ed*dist + fx, 0.0f), (float)(WW-1));
        L.w = fminf(fmaxf(ay_ed*dist + fy, 0.0f), (float)(HH-1));
        ((float4*)g_lines)[r*NPIX + idx] = L;
    }

    // --- 3x3 NMS on jloc + compaction of candidates ---
    float a = jloc[idx];
    float m = -1e30f;
    #pragma unroll
    for (int dy = -1; dy <= 1; ++dy) {
        int yy = y + dy;
        if (yy < 0 || yy >= HH) continue;
        #pragma unroll
        for (int dx = -1; dx <= 1; ++dx) {
            int xx = x + dx;
            if (xx < 0 || xx >= WW) continue;
            m = fmaxf(m, jloc[yy*WW + xx]);
        }
    }
    float v = (a == m) ? a : 0.0f;
    if (v > 0.0f) {
        int p = atomicAdd(&g_cnt[0], 1);
        g_cand_v[p] = v;
        g_cand_i[p] = idx;
    } else {
        int p = atomicAdd(&g_cnt[1], 1);
        g_zero_i[p] = idx;
    }
}

// One warp per line, one lane per t-point, 16 channels per thread.
__global__ void __launch_bounds__(256) k_loi(float* __restrict__ out)
{
    int lane = threadIdx.x & 31;
    int line = (blockIdx.x * blockDim.x + threadIdx.x) >> 5;

    float4 L = ((const float4*)g_lines)[line];   // warp-broadcast
    float tf = (float)lane * (1.0f / 31.0f);     // tspan = linspace(0,1,32)
    // pts = U*t + V*(1-t) - 0.5, U = (x_st,y_st), V = (x_ed,y_ed)
    float px = L.x*tf + L.z*(1.0f - tf) - 0.5f;
    float py = L.y*tf + L.w*(1.0f - tf) - 0.5f;

    float px0 = fminf(fmaxf(floorf(px), 0.0f), (float)(WW-1));
    float py0 = fminf(fmaxf(floorf(py), 0.0f), (float)(HH-1));
    float px1 = fminf(px0 + 1.0f, (float)(WW-1));
    float py1 = fminf(py0 + 1.0f, (float)(HH-1));
    float wx0 = px1 - px, wx1 = px - px0;
    float wy0 = py1 - py, wy1 = py - py0;
    float w00 = wy0*wx0, w10 = wy1*wx0, w01 = wy0*wx1, w11 = wy1*wx1;
    int ix0 = (int)px0, iy0 = (int)py0, ix1 = (int)px1, iy1 = (int)py1;

    const float4* f00 = (const float4*)&g_tfeat[(iy0*WW + ix0)*CC];
    const float4* f10 = (const float4*)&g_tfeat[(iy1*WW + ix0)*CC];
    const float4* f01 = (const float4*)&g_tfeat[(iy0*WW + ix1)*CC];
    const float4* f11 = (const float4*)&g_tfeat[(iy1*WW + ix1)*CC];

    float acc[CC];
    #pragma unroll
    for (int q = 0; q < 4; ++q) {
        float4 a = f00[q], b = f10[q], c = f01[q], d = f11[q];
        acc[4*q+0] = a.x*w00 + b.x*w10 + c.x*w01 + d.x*w11;
        acc[4*q+1] = a.y*w00 + b.y*w10 + c.y*w01 + d.y*w11;
        acc[4*q+2] = a.z*w00 + b.z*w10 + c.z*w01 + d.z*w11;
        acc[4*q+3] = a.w*w00 + b.w*w10 + c.w*w01 + d.w*w11;
    }

    // loi[line][c*32 + t]; per-c store is 128B coalesced across the warp
    float* row = out + (size_t)line * (CC*NPTS) + lane;
    #pragma unroll
    for (int c = 0; c < CC; ++c) row[c*NPTS] = acc[c];
}

// Parallel rank-by-count: one thread per candidate i, j-list staged in smem
// tiles. Grid covers all NPIX possible candidates; matches jax.lax.top_k
// stable ordering via (v desc, idx asc) tie-break.
__global__ void __launch_bounds__(256) k_topk(const float* __restrict__ joff,
                                              const int* __restrict__ topk,
                                              float* __restrict__ out)
{
    __shared__ float sv[TTILE];
    __shared__ int   si[TTILE];

    int K = topk[0];
    int M = g_cnt[0];
    float* junc = out + (size_t)LOI_ELEMS;
    float* sc   = junc + 2*(size_t)K;

    int i = blockIdx.x * blockDim.x + threadIdx.x;
    bool active = (i < M);
    float v = 0.0f; int id = 0;
    if (active) { v = g_cand_v[i]; id = g_cand_i[i]; }

    int rank = 0;
    for (int jt = 0; jt < M; jt += TTILE) {
        int n = min(TTILE, M - jt);
        __syncthreads();
        for (int t = threadIdx.x; t < n; t += blockDim.x) {
            sv[t] = g_cand_v[jt + t];
            si[t] = g_cand_i[jt + t];
        }
        __syncthreads();
        if (active) {
            for (int t = 0; t < n; ++t) {
                float vj = sv[t];
                rank += (vj > v) || (vj == v && si[t] < id);
            }
        }
    }
    if (active && rank < K) {
        sc[rank] = v;
        junc[2*rank+0] = (float)(id & (WW-1)) + joff[id]        + 0.5f;
        junc[2*rank+1] = (float)(id >> 7)     + joff[NPIX + id] + 0.5f;
    }

    // fallback: fewer positive maxima than K -> fill with zeros in index order
    if (M < K) {
        int Z = g_cnt[1];
        bool zact = (i < Z);
        int zid = 0;
        if (zact) zid = g_zero_i[i];
        int zr = 0;
        for (int jt = 0; jt < Z; jt += TTILE) {
            int n = min(TTILE, Z - jt);
            __syncthreads();
            for (int t = threadIdx.x; t < n; t += blockDim.x)
                si[t] = g_zero_i[jt + t];
            __syncthreads();
            if (zact)
                for (int t = 0; t < n; ++t) zr += (si[t] < zid);
        }
        int rk = M + zr;
        if (zact && rk < K) {
            sc[rk] = 0.0f;
            junc[2*rk+0] = (float)(zid & (WW-1)) + joff[zid]        + 0.5f;
            junc[2*rk+1] = (float)(zid >> 7)     + joff[NPIX + zid] + 0.5f;
        }
    }
}

extern "C" void kernel_launch(void* const* d_in, const int* in_sizes, int n_in,
                              void* d_out, int out_size)
{
    const float* md   = (const float*)d_in[0];
    const float* dis  = (const float*)d_in[1];
    const float* res  = (const float*)d_in[2];
    const float* feat = (const float*)d_in[3];
    const float* jloc = (const float*)d_in[4];
    const float* joff = (const float*)d_in[5];
    const int*   topk = (const int*)d_in[6];
    float* out = (float*)d_out;

    k_reset<<<1, 1>>>();
    k_prep<<<NPIX/256, 256>>>(md, dis, res, feat, jloc);
    k_loi<<<NLINES/8, 256>>>(out);          // 10240 blocks x 8 warps, 1 line/warp
    k_topk<<<NPIX/256, 256>>>(joff, topk, out);  // 64 blocks, whole chip
}

// round 3
// speedup vs baseline: 7.1892x; 2.2432x over previous
#include <cuda_runtime.h>

#define HH 128
#define WW 128
#define CC 16
#define NPIX (HH*WW)
#define NRES 5
#define NLINES (NRES*NPIX)
#define NPTS 32
#define SCALE 5.0f
#define LOI_ELEMS (NLINES*CC*NPTS)

// scratch (no allocations allowed)
__device__ float g_lines[NLINES*4];      // 1.31 MB  (x_st,y_st,x_ed,y_ed)
__device__ float g_tfeat[NPIX*CC];       // 1 MB, channel-last transposed features
__device__ float g_cand_v[NPIX];
__device__ int   g_cand_i[NPIX];
__device__ int   g_zero_i[NPIX];
__device__ int   g_cnt[2];

__global__ void k_reset() { g_cnt[0] = 0; g_cnt[1] = 0; }

__global__ void k_prep(const float* __restrict__ md, const float* __restrict__ dis,
                       const float* __restrict__ res, const float* __restrict__ feat,
                       const float* __restrict__ jloc)
{
    int idx = blockIdx.x * blockDim.x + threadIdx.x;
    if (idx >= NPIX) return;
    int x = idx & (WW-1), y = idx >> 7;

    // --- transpose features to [y][x][c] (channel-last) ---
    #pragma unroll
    for (int c = 0; c < CC; ++c)
        g_tfeat[idx*CC + c] = feat[c*NPIX + idx];

    // --- hafm decoding: per-pixel trig hoisted over 5 residuals ---
    const float PI = 3.14159265358979323846f;
    float md0 = md[idx], md1 = md[NPIX+idx], md2 = md[2*NPIX+idx];
    float md_un = (md0 - 0.5f) * (2.0f * PI);
    float cs  = cosf(md_un);
    float ss  = sinf(md_un);
    float yst = tanf(md1 * (PI * 0.5f));
    float yed = tanf(-md2 * (PI * 0.5f));
    float d0 = dis[idx], r0 = res[idx];
    float ax_st = cs - ss*yst, ay_st = ss + cs*yst;
    float ax_ed = cs - ss*yed, ay_ed = ss + cs*yed;
    float fx = (float)x, fy = (float)y;
    #pragma unroll
    for (int r = 0; r < NRES; ++r) {
        float sign = (float)(r - 2);
        float dist = fminf(fmaxf(d0 + r0*sign, 0.0f), 1.0f) * SCALE;
        float4 L;
        L.x = fminf(fmaxf(ax_st*dist + fx, 0.0f), (float)(WW-1));
        L.y = fminf(fmaxf(ay_st*dist + fy, 0.0f), (float)(HH-1));
        L.z = fminf(fmaxf(ax_ed*dist + fx, 0.0f), (float)(WW-1));
        L.w = fminf(fmaxf(ay_ed*dist + fy, 0.0f), (float)(HH-1));
        ((float4*)g_lines)[r*NPIX + idx] = L;
    }

    // --- 3x3 NMS on jloc + compaction of candidates ---
    float a = jloc[idx];
    float m = -1e30f;
    #pragma unroll
    for (int dy = -1; dy <= 1; ++dy) {
        int yy = y + dy;
        if (yy < 0 || yy >= HH) continue;
        #pragma unroll
        for (int dx = -1; dx <= 1; ++dx) {
            int xx = x + dx;
            if (xx < 0 || xx >= WW) continue;
            m = fmaxf(m, jloc[yy*WW + xx]);
        }
    }
    float v = (a == m) ? a : 0.0f;
    if (v > 0.0f) {
        int p = atomicAdd(&g_cnt[0], 1);
        g_cand_v[p] = v;
        g_cand_i[p] = idx;
    } else {
        int p = atomicAdd(&g_cnt[1], 1);
        g_zero_i[p] = idx;
    }
}

// One warp per line, one lane per t-point, 16 channels per thread.
__global__ void __launch_bounds__(256) k_loi(float* __restrict__ out)
{
    int lane = threadIdx.x & 31;
    int line = (blockIdx.x * blockDim.x + threadIdx.x) >> 5;

    float4 L = ((const float4*)g_lines)[line];   // warp-broadcast
    float tf = (float)lane * (1.0f / 31.0f);     // tspan = linspace(0,1,32)
    // pts = U*t + V*(1-t) - 0.5, U = (x_st,y_st), V = (x_ed,y_ed)
    float px = L.x*tf + L.z*(1.0f - tf) - 0.5f;
    float py = L.y*tf + L.w*(1.0f - tf) - 0.5f;

    float px0 = fminf(fmaxf(floorf(px), 0.0f), (float)(WW-1));
    float py0 = fminf(fmaxf(floorf(py), 0.0f), (float)(HH-1));
    float px1 = fminf(px0 + 1.0f, (float)(WW-1));
    float py1 = fminf(py0 + 1.0f, (float)(HH-1));
    float wx0 = px1 - px, wx1 = px - px0;
    float wy0 = py1 - py, wy1 = py - py0;
    float w00 = wy0*wx0, w10 = wy1*wx0, w01 = wy0*wx1, w11 = wy1*wx1;
    int ix0 = (int)px0, iy0 = (int)py0, ix1 = (int)px1, iy1 = (int)py1;

    const float4* f00 = (const float4*)&g_tfeat[(iy0*WW + ix0)*CC];
    const float4* f10 = (const float4*)&g_tfeat[(iy1*WW + ix0)*CC];
    const float4* f01 = (const float4*)&g_tfeat[(iy0*WW + ix1)*CC];
    const float4* f11 = (const float4*)&g_tfeat[(iy1*WW + ix1)*CC];

    float acc[CC];
    #pragma unroll
    for (int q = 0; q < 4; ++q) {
        float4 a = f00[q], b = f10[q], c = f01[q], d = f11[q];
        acc[4*q+0] = a.x*w00 + b.x*w10 + c.x*w01 + d.x*w11;
        acc[4*q+1] = a.y*w00 + b.y*w10 + c.y*w01 + d.y*w11;
        acc[4*q+2] = a.z*w00 + b.z*w10 + c.z*w01 + d.z*w11;
        acc[4*q+3] = a.w*w00 + b.w*w10 + c.w*w01 + d.w*w11;
    }

    // loi[line][c*32 + t]; per-c store is 128B coalesced across the warp
    float* row = out + (size_t)line * (CC*NPTS) + lane;
    #pragma unroll
    for (int c = 0; c < CC; ++c) row[c*NPTS] = acc[c];
}

// Warp-per-candidate rank-by-count. Lanes stride the j-loop (coalesced);
// bitwise |/& (no short-circuit -> no BSSY/BSYNC diamonds). Matches
// jax.lax.top_k stable ordering via (v desc, idx asc).
__global__ void __launch_bounds__(256) k_topk(const float* __restrict__ joff,
                                              const int* __restrict__ topk,
                                              float* __restrict__ out)
{
    int K = topk[0];
    int M = g_cnt[0];
    float* junc = out + (size_t)LOI_ELEMS;
    float* sc   = junc + 2*(size_t)K;

    int lane = threadIdx.x & 31;
    int i = (blockIdx.x * blockDim.x + threadIdx.x) >> 5;   // warp id == candidate

    if (i < M) {
        float v = g_cand_v[i];      // warp-broadcast
        int  id = g_cand_i[i];
        int rank = 0;
        for (int j = lane; j < M; j += 32) {
            float vj = g_cand_v[j];
            int   ij = g_cand_i[j];
            rank += (int)((vj > v) | ((vj == v) & (ij < id)));
        }
        #pragma unroll
        for (int o = 16; o; o >>= 1) rank += __shfl_xor_sync(0xffffffffu, rank, o);
        if (lane == 0 && rank < K) {
            sc[rank] = v;
            junc[2*rank+0] = (float)(id & (WW-1)) + joff[id]        + 0.5f;
            junc[2*rank+1] = (float)(id >> 7)     + joff[NPIX + id] + 0.5f;
        }
    }

    // fallback: fewer positive maxima than K -> fill with zeros in index order
    if (M < K && i < g_cnt[1]) {
        int Z = g_cnt[1];
        int zid = g_zero_i[i];
        int zr = 0;
        for (int j = lane; j < Z; j += 32)
            zr += (int)(g_zero_i[j] < zid);
        #pragma unroll
        for (int o = 16; o; o >>= 1) zr += __shfl_xor_sync(0xffffffffu, zr, o);
        int rk = M + zr;
        if (lane == 0 && rk < K) {
            sc[rk] = 0.0f;
            junc[2*rk+0] = (float)(zid & (WW-1)) + joff[zid]        + 0.5f;
            junc[2*rk+1] = (float)(zid >> 7)     + joff[NPIX + zid] + 0.5f;
        }
    }
}

extern "C" void kernel_launch(void* const* d_in, const int* in_sizes, int n_in,
                              void* d_out, int out_size)
{
    const float* md   = (const float*)d_in[0];
    const float* dis  = (const float*)d_in[1];
    const float* res  = (const float*)d_in[2];
    const float* feat = (const float*)d_in[3];
    const float* jloc = (const float*)d_in[4];
    const float* joff = (const float*)d_in[5];
    const int*   topk = (const int*)d_in[6];
    float* out = (float*)d_out;

    k_reset<<<1, 1>>>();
    k_prep<<<NPIX/256, 256>>>(md, dis, res, feat, jloc);
    k_topk<<<NPIX*32/256, 256>>>(joff, topk, out);  // 1 warp per candidate
    k_loi<<<NLINES/8, 256>>>(out);                  // 1 line per warp
}

// round 4
// speedup vs baseline: 9.8118x; 1.3648x over previous
#include <cuda_runtime.h>
#include <cuda_fp16.h>

#define HH 128
#define WW 128
#define CC 16
#define NPIX (HH*WW)
#define NRES 5
#define NLINES (NRES*NPIX)
#define NPTS 32
#define SCALE 5.0f
#define LOI_ELEMS (NLINES*CC*NPTS)

// scratch (no allocations allowed)
__device__ float  g_lines[NLINES*4];     // 1.31 MB  (x_st,y_st,x_ed,y_ed)
__device__ __half g_tfeat[NPIX*CC];      // 0.5 MB, channel-last fp16 features
__device__ float  g_cand_v[NPIX];
__device__ int    g_cand_i[NPIX];
__device__ int    g_zero_i[NPIX];
__device__ int    g_cnt[2];

__global__ void k_reset() { g_cnt[0] = 0; g_cnt[1] = 0; }

__global__ void __launch_bounds__(256) k_prep(
    const float* __restrict__ md, const float* __restrict__ dis,
    const float* __restrict__ res, const float* __restrict__ feat,
    const float* __restrict__ jloc)
{
    __shared__ float s[CC*257];
    int tid = threadIdx.x;
    int idx = blockIdx.x * 256 + tid;
    int x = idx & (WW-1), y = idx >> 7;

    // --- stage features (coalesced loads), pack to fp16 channel-last ---
    #pragma unroll
    for (int c = 0; c < CC; ++c)
        s[c*257 + tid] = feat[c*NPIX + idx];
    __syncthreads();
    {
        unsigned r[8];
        #pragma unroll
        for (int j = 0; j < 8; ++j) {
            __half2 h = __floats2half2_rn(s[(2*j)*257 + tid], s[(2*j+1)*257 + tid]);
            r[j] = *(unsigned*)&h;
        }
        uint4* dst = (uint4*)&g_tfeat[idx*CC];
        dst[0] = make_uint4(r[0], r[1], r[2], r[3]);
        dst[1] = make_uint4(r[4], r[5], r[6], r[7]);
    }

    // --- hafm decoding: per-pixel trig hoisted over 5 residuals ---
    const float PI = 3.14159265358979323846f;
    float md0 = md[idx], md1 = md[NPIX+idx], md2 = md[2*NPIX+idx];
    float md_un = (md0 - 0.5f) * (2.0f * PI);
    float cs  = cosf(md_un);
    float ss  = sinf(md_un);
    float yst = tanf(md1 * (PI * 0.5f));
    float yed = tanf(-md2 * (PI * 0.5f));
    float d0 = dis[idx], r0 = res[idx];
    float ax_st = cs - ss*yst, ay_st = ss + cs*yst;
    float ax_ed = cs - ss*yed, ay_ed = ss + cs*yed;
    float fx = (float)x, fy = (float)y;
    #pragma unroll
    for (int r = 0; r < NRES; ++r) {
        float sign = (float)(r - 2);
        float dist = fminf(fmaxf(d0 + r0*sign, 0.0f), 1.0f) * SCALE;
        float4 L;
        L.x = fminf(fmaxf(ax_st*dist + fx, 0.0f), (float)(WW-1));
        L.y = fminf(fmaxf(ay_st*dist + fy, 0.0f), (float)(HH-1));
        L.z = fminf(fmaxf(ax_ed*dist + fx, 0.0f), (float)(WW-1));
        L.w = fminf(fmaxf(ay_ed*dist + fy, 0.0f), (float)(HH-1));
        ((float4*)g_lines)[r*NPIX + idx] = L;
    }

    // --- 3x3 NMS on jloc + compaction of candidates ---
    float a = jloc[idx];
    float m = -1e30f;
    #pragma unroll
    for (int dy = -1; dy <= 1; ++dy) {
        int yy = y + dy;
        if (yy < 0 || yy >= HH) continue;
        #pragma unroll
        for (int dx = -1; dx <= 1; ++dx) {
            int xx = x + dx;
            if (xx < 0 || xx >= WW) continue;
            m = fmaxf(m, jloc[yy*WW + xx]);
        }
    }
    float v = (a == m) ? a : 0.0f;
    if (v > 0.0f) {
        int p = atomicAdd(&g_cnt[0], 1);
        g_cand_v[p] = v;
        g_cand_i[p] = idx;
    } else {
        int p = atomicAdd(&g_cnt[1], 1);
        g_zero_i[p] = idx;
    }
}

// One warp per line. lane = (c2, tg): 8 channels x 2 consecutive t-points
// per thread. fp16 feature loads: one LDG.128 = 8 channels of one corner.
__global__ void __launch_bounds__(256) k_loi(float* __restrict__ out)
{
    int lane = threadIdx.x & 31;
    int line = (blockIdx.x * blockDim.x + threadIdx.x) >> 5;
    int c2 = lane >> 4;          // channel group: 0 or 1 (8 channels each)
    int tg = lane & 15;          // t-pair group: t = 2*tg + k

    float4 L = ((const float4*)g_lines)[line];   // warp-broadcast

    const __half* fb = g_tfeat + c2*8;
    float2 acc[2][4];            // [k][channel-pair]

    #pragma unroll
    for (int k = 0; k < 2; ++k) {
        float tf = (float)(2*tg + k) * (1.0f / 31.0f);
        float px = L.x*tf + L.z*(1.0f - tf) - 0.5f;
        float py = L.y*tf + L.w*(1.0f - tf) - 0.5f;

        float px0 = fminf(fmaxf(floorf(px), 0.0f), (float)(WW-1));
        float py0 = fminf(fmaxf(floorf(py), 0.0f), (float)(HH-1));
        float px1 = fminf(px0 + 1.0f, (float)(WW-1));
        float py1 = fminf(py0 + 1.0f, (float)(HH-1));
        float wx0 = px1 - px, wx1 = px - px0;
        float wy0 = py1 - py, wy1 = py - py0;
        float w00 = wy0*wx0, w10 = wy1*wx0, w01 = wy0*wx1, w11 = wy1*wx1;
        int ix0 = (int)px0, iy0 = (int)py0, ix1 = (int)px1, iy1 = (int)py1;

        uint4 q00 = *(const uint4*)(fb + (iy0*WW + ix0)*CC);
        uint4 q10 = *(const uint4*)(fb + (iy1*WW + ix0)*CC);
        uint4 q01 = *(const uint4*)(fb + (iy0*WW + ix1)*CC);
        uint4 q11 = *(const uint4*)(fb + (iy1*WW + ix1)*CC);

        const unsigned* u00 = (const unsigned*)&q00;
        const unsigned* u10 = (const unsigned*)&q10;
        const unsigned* u01 = (const unsigned*)&q01;
        const unsigned* u11 = (const unsigned*)&q11;

        #pragma unroll
        for (int p = 0; p < 4; ++p) {
            float2 a = __half22float2(*(const __half2*)&u00[p]);
            float2 b = __half22float2(*(const __half2*)&u10[p]);
            float2 c = __half22float2(*(const __half2*)&u01[p]);
            float2 d = __half22float2(*(const __half2*)&u11[p]);
            acc[k][p].x = a.x*w00 + b.x*w10 + c.x*w01 + d.x*w11;
            acc[k][p].y = a.y*w00 + b.y*w10 + c.y*w01 + d.y*w11;
        }
    }

    // out[line][c*32 + t]; float2 covers t = 2tg, 2tg+1
    float* row = out + (size_t)line * (CC*NPTS) + c2*(8*NPTS) + 2*tg;
    #pragma unroll
    for (int p = 0; p < 4; ++p) {
        *(float2*)(row + (2*p  )*NPTS) = make_float2(acc[0][p].x, acc[1][p].x);
        *(float2*)(row + (2*p+1)*NPTS) = make_float2(acc[0][p].y, acc[1][p].y);
    }
}

// Warp-per-candidate rank-by-count (stable (v desc, idx asc) = jax.lax.top_k).
__global__ void __launch_bounds__(256) k_topk(const float* __restrict__ joff,
                                              const int* __restrict__ topk,
                                              float* __restrict__ out)
{
    int K = topk[0];
    int M = g_cnt[0];
    float* junc = out + (size_t)LOI_ELEMS;
    float* sc   = junc + 2*(size_t)K;

    int lane = threadIdx.x & 31;
    int i = (blockIdx.x * blockDim.x + threadIdx.x) >> 5;

    if (i < M) {
        float v = g_cand_v[i];
        int  id = g_cand_i[i];
        int rank = 0;
        for (int j = lane; j < M; j += 32) {
            float vj = g_cand_v[j];
            int   ij = g_cand_i[j];
            rank += (int)((vj > v) | ((vj == v) & (ij < id)));
        }
        #pragma unroll
        for (int o = 16; o; o >>= 1) rank += __shfl_xor_sync(0xffffffffu, rank, o);
        if (lane == 0 && rank < K) {
            sc[rank] = v;
            junc[2*rank+0] = (float)(id & (WW-1)) + joff[id]        + 0.5f;
            junc[2*rank+1] = (float)(id >> 7)     + joff[NPIX + id] + 0.5f;
        }
    }

    if (M < K && i < g_cnt[1]) {
        int Z = g_cnt[1];
        int zid = g_zero_i[i];
        int zr = 0;
        for (int j = lane; j < Z; j += 32)
            zr += (int)(g_zero_i[j] < zid);
        #pragma unroll
        for (int o = 16; o; o >>= 1) zr += __shfl_xor_sync(0xffffffffu, zr, o);
        int rk = M + zr;
        if (lane == 0 && rk < K) {
            sc[rk] = 0.0f;
            junc[2*rk+0] = (float)(zid & (WW-1)) + joff[zid]        + 0.5f;
            junc[2*rk+1] = (float)(zid >> 7)     + joff[NPIX + zid] + 0.5f;
        }
    }
}

extern "C" void kernel_launch(void* const* d_in, const int* in_sizes, int n_in,
                              void* d_out, int out_size)
{
    const float* md   = (const float*)d_in[0];
    const float* dis  = (const float*)d_in[1];
    const float* res  = (const float*)d_in[2];
    const float* feat = (const float*)d_in[3];
    const float* jloc = (const float*)d_in[4];
    const float* joff = (const float*)d_in[5];
    const int*   topk = (const int*)d_in[6];
    float* out = (float*)d_out;

    k_reset<<<1, 1>>>();
    k_prep<<<NPIX/256, 256>>>(md, dis, res, feat, jloc);
    k_topk<<<NPIX*32/256, 256>>>(joff, topk, out);  // 1 warp per candidate
    k_loi<<<NLINES/8, 256>>>(out);                  // 1 line per warp
}

// round 6
// speedup vs baseline: 10.5715x; 1.0774x over previous
#include <cuda_runtime.h>
#include <cuda_fp16.h>

#define HH 128
#define WW 128
#define CC 16
#define NPIX (HH*WW)
#define NRES 5
#define NLINES (NRES*NPIX)
#define NPTS 32
#define SCALE 5.0f
#define LOI_ELEMS (NLINES*CC*NPTS)
#define TOPK_BLOCKS (NPIX/8)        // 2048 blocks, 1 warp per candidate
#define LOI_BLOCKS  (NLINES/8)      // 10240 blocks, 1 warp per line

// scratch (no allocations allowed)
__device__ __half g_tfeat[NPIX*CC];      // 0.5 MB, channel-last fp16 features
__device__ float  g_cand_v[NPIX];
__device__ int    g_cand_i[NPIX];
__device__ int    g_zero_i[NPIX];
__device__ int    g_cnt[2];

__global__ void k_reset() { g_cnt[0] = 0; g_cnt[1] = 0; }

// transpose features to fp16 channel-last + 3x3 NMS + candidate compaction
__global__ void __launch_bounds__(256) k_prep(
    const float* __restrict__ feat, const float* __restrict__ jloc)
{
    __shared__ float s[CC*257];
    int tid = threadIdx.x;
    int idx = blockIdx.x * 256 + tid;
    int x = idx & (WW-1), y = idx >> 7;

    #pragma unroll
    for (int c = 0; c < CC; ++c)
        s[c*257 + tid] = feat[c*NPIX + idx];
    __syncthreads();
    {
        unsigned r[8];
        #pragma unroll
        for (int j = 0; j < 8; ++j) {
            __half2 h = __floats2half2_rn(s[(2*j)*257 + tid], s[(2*j+1)*257 + tid]);
            r[j] = *(unsigned*)&h;
        }
        uint4* dst = (uint4*)&g_tfeat[idx*CC];
        dst[0] = make_uint4(r[0], r[1], r[2], r[3]);
        dst[1] = make_uint4(r[4], r[5], r[6], r[7]);
    }

    float a = jloc[idx];
    float m = -1e30f;
    #pragma unroll
    for (int dy = -1; dy <= 1; ++dy) {
        int yy = y + dy;
        if (yy < 0 || yy >= HH) continue;
        #pragma unroll
        for (int dx = -1; dx <= 1; ++dx) {
            int xx = x + dx;
            if (xx < 0 || xx >= WW) continue;
            m = fmaxf(m, jloc[yy*WW + xx]);
        }
    }
    float v = (a == m) ? a : 0.0f;
    if (v > 0.0f) {
        int p = atomicAdd(&g_cnt[0], 1);
        g_cand_v[p] = v;
        g_cand_i[p] = idx;
    } else {
        int p = atomicAdd(&g_cnt[1], 1);
        g_zero_i[p] = idx;
    }
}

// Merged kernel: first TOPK_BLOCKS do rank-by-count top-k; the rest do LOI.
__global__ void __launch_bounds__(256) k_main(
    float* __restrict__ out,
    const float* __restrict__ md, const float* __restrict__ dis,
    const float* __restrict__ res, const float* __restrict__ joff,
    const int* __restrict__ topk)
{
    int lane = threadIdx.x & 31;

    if (blockIdx.x < TOPK_BLOCKS) {
        // ---- top-k: warp-per-candidate, stable (v desc, idx asc) ----
        int K = topk[0];
        int M = g_cnt[0];
        float* junc = out + (size_t)LOI_ELEMS;
        float* sc   = junc + 2*(size_t)K;
        int i = (blockIdx.x * blockDim.x + threadIdx.x) >> 5;

        if (i < M) {
            float v = g_cand_v[i];
            int  id = g_cand_i[i];
            int rank = 0;
            for (int j = lane; j < M; j += 32) {
                float vj = g_cand_v[j];
                int   ij = g_cand_i[j];
                rank += (int)((vj > v) | ((vj == v) & (ij < id)));
            }
            #pragma unroll
            for (int o = 16; o; o >>= 1) rank += __shfl_xor_sync(0xffffffffu, rank, o);
            if (lane == 0 && rank < K) {
                sc[rank] = v;
                junc[2*rank+0] = (float)(id & (WW-1)) + joff[id]        + 0.5f;
                junc[2*rank+1] = (float)(id >> 7)     + joff[NPIX + id] + 0.5f;
            }
        }
        if (M < K && i < g_cnt[1]) {
            int Z = g_cnt[1];
            int zid = g_zero_i[i];
            int zr = 0;
            for (int j = lane; j < Z; j += 32)
                zr += (int)(g_zero_i[j] < zid);
            #pragma unroll
            for (int o = 16; o; o >>= 1) zr += __shfl_xor_sync(0xffffffffu, zr, o);
            int rk = M + zr;
            if (lane == 0 && rk < K) {
                sc[rk] = 0.0f;
                junc[2*rk+0] = (float)(zid & (WW-1)) + joff[zid]        + 0.5f;
                junc[2*rk+1] = (float)(zid >> 7)     + joff[NPIX + zid] + 0.5f;
            }
        }
        return;
    }

    // ---- LOI: one warp per line; hafm decoded in-warp (broadcast loads) ----
    int line = ((blockIdx.x - TOPK_BLOCKS) * blockDim.x + threadIdx.x) >> 5;
    int pix = line & (NPIX-1);
    int r   = line >> 14;               // residual index 0..4
    int x = pix & (WW-1), y = pix >> 7;

    const float PI = 3.14159265358979323846f;
    float md0 = md[pix], md1 = md[NPIX+pix], md2 = md[2*NPIX+pix];
    float d0 = dis[pix], r0 = res[pix];
    float md_un = (md0 - 0.5f) * (2.0f * PI);
    float cs  = cosf(md_un);
    float ss  = sinf(md_un);
    float yst = tanf(md1 * (PI * 0.5f));
    float yed = tanf(-md2 * (PI * 0.5f));
    float dist = fminf(fmaxf(d0 + r0*(float)(r-2), 0.0f), 1.0f) * SCALE;
    float fx = (float)x, fy = (float)y;
    float4 L;
    L.x = fminf(fmaxf((cs - ss*yst)*dist + fx, 0.0f), (float)(WW-1));
    L.y = fminf(fmaxf((ss + cs*yst)*dist + fy, 0.0f), (float)(HH-1));
    L.z = fminf(fmaxf((cs - ss*yed)*dist + fx, 0.0f), (float)(WW-1));
    L.w = fminf(fmaxf((ss + cs*yed)*dist + fy, 0.0f), (float)(HH-1));

    int c2 = lane >> 4;          // channel group: 0 or 1 (8 channels each)
    int tg = lane & 15;          // t-pair group: t = 2*tg + k

    const __half* fb = g_tfeat + c2*8;
    float2 acc[2][4];

    #pragma unroll
    for (int k = 0; k < 2; ++k) {
        float tf = (float)(2*tg + k) * (1.0f / 31.0f);
        float px = L.x*tf + L.z*(1.0f - tf) - 0.5f;
        float py = L.y*tf + L.w*(1.0f - tf) - 0.5f;

        float px0 = fminf(fmaxf(floorf(px), 0.0f), (float)(WW-1));
        float py0 = fminf(fmaxf(floorf(py), 0.0f), (float)(HH-1));
        float px1 = fminf(px0 + 1.0f, (float)(WW-1));
        float py1 = fminf(py0 + 1.0f, (float)(HH-1));
        float wx0 = px1 - px, wx1 = px - px0;
        float wy0 = py1 - py, wy1 = py - py0;
        float w00 = wy0*wx0, w10 = wy1*wx0, w01 = wy0*wx1, w11 = wy1*wx1;
        int ix0 = (int)px0, iy0 = (int)py0, ix1 = (int)px1, iy1 = (int)py1;

        uint4 q00 = *(const uint4*)(fb + (iy0*WW + ix0)*CC);
        uint4 q10 = *(const uint4*)(fb + (iy1*WW + ix0)*CC);
        uint4 q01 = *(const uint4*)(fb + (iy0*WW + ix1)*CC);
        uint4 q11 = *(const uint4*)(fb + (iy1*WW + ix1)*CC);

        const unsigned* u00 = (const unsigned*)&q00;
        const unsigned* u10 = (const unsigned*)&q10;
        const unsigned* u01 = (const unsigned*)&q01;
        const unsigned* u11 = (const unsigned*)&q11;

        #pragma unroll
        for (int p = 0; p < 4; ++p) {
            float2 a = __half22float2(*(const __half2*)&u00[p]);
            float2 b = __half22float2(*(const __half2*)&u10[p]);
            float2 c = __half22float2(*(const __half2*)&u01[p]);
            float2 d = __half22float2(*(const __half2*)&u11[p]);
            acc[k][p].x = a.x*w00 + b.x*w10 + c.x*w01 + d.x*w11;
            acc[k][p].y = a.y*w00 + b.y*w10 + c.y*w01 + d.y*w11;
        }
    }

    float* row = out + (size_t)line * (CC*NPTS) + c2*(8*NPTS) + 2*tg;
    #pragma unroll
    for (int p = 0; p < 4; ++p) {
        *(float2*)(row + (2*p  )*NPTS) = make_float2(acc[0][p].x, acc[1][p].x);
        *(float2*)(row + (2*p+1)*NPTS) = make_float2(acc[0][p].y, acc[1][p].y);
    }
}

extern "C" void kernel_launch(void* const* d_in, const int* in_sizes, int n_in,
                              void* d_out, int out_size)
{
    const float* md   = (const float*)d_in[0];
    const float* dis  = (const float*)d_in[1];
    const float* res  = (const float*)d_in[2];
    const float* feat = (const float*)d_in[3];
    const float* jloc = (const float*)d_in[4];
    const float* joff = (const float*)d_in[5];
    const int*   topk = (const int*)d_in[6];
    float* out = (float*)d_out;

    k_reset<<<1, 1>>>();
    k_prep<<<NPIX/256, 256>>>(feat, jloc);
    k_main<<<TOPK_BLOCKS + LOI_BLOCKS, 256>>>(out, md, dis, res, joff, topk);
}

// round 7
// speedup vs baseline: 10.8346x; 1.0249x over previous
#include <cuda_runtime.h>
#include <cuda_fp16.h>

#define HH 128
#define WW 128
#define CC 16
#define NPIX (HH*WW)
#define NRES 5
#define NLINES (NRES*NPIX)
#define NPTS 32
#define SCALE 5.0f
#define LOI_ELEMS (NLINES*CC*NPTS)
#define TOPK_BLOCKS (NPIX/8)        // 2048 blocks, 1 warp per candidate
#define LOI_BLOCKS  (NLINES/8)      // 10240 blocks, 1 warp per line

// scratch (no allocations allowed)
__device__ __half g_tfeat[NPIX*CC];      // 0.5 MB, channel-last fp16 features
__device__ float  g_cand_v[NPIX];
__device__ int    g_cand_i[NPIX];
__device__ int    g_zero_i[NPIX];
__device__ int    g_cnt[2];              // zero-init; self-resetting (see k_main)
__device__ int    g_done;                // zero-init; self-resetting

// transpose features to fp16 channel-last + 3x3 NMS + candidate compaction
__global__ void __launch_bounds__(256) k_prep(
    const float* __restrict__ feat, const float* __restrict__ jloc)
{
    __shared__ float s[CC*257];
    int tid = threadIdx.x;
    int idx = blockIdx.x * 256 + tid;
    int x = idx & (WW-1), y = idx >> 7;

    #pragma unroll
    for (int c = 0; c < CC; ++c)
        s[c*257 + tid] = feat[c*NPIX + idx];
    __syncthreads();
    {
        unsigned r[8];
        #pragma unroll
        for (int j = 0; j < 8; ++j) {
            __half2 h = __floats2half2_rn(s[(2*j)*257 + tid], s[(2*j+1)*257 + tid]);
            r[j] = *(unsigned*)&h;
        }
        uint4* dst = (uint4*)&g_tfeat[idx*CC];
        dst[0] = make_uint4(r[0], r[1], r[2], r[3]);
        dst[1] = make_uint4(r[4], r[5], r[6], r[7]);
    }

    float a = jloc[idx];
    float m = -1e30f;
    #pragma unroll
    for (int dy = -1; dy <= 1; ++dy) {
        int yy = y + dy;
        if (yy < 0 || yy >= HH) continue;
        #pragma unroll
        for (int dx = -1; dx <= 1; ++dx) {
            int xx = x + dx;
            if (xx < 0 || xx >= WW) continue;
            m = fmaxf(m, jloc[yy*WW + xx]);
        }
    }
    float v = (a == m) ? a : 0.0f;
    if (v > 0.0f) {
        int p = atomicAdd(&g_cnt[0], 1);
        g_cand_v[p] = v;
        g_cand_i[p] = idx;
    } else {
        int p = atomicAdd(&g_cnt[1], 1);
        g_zero_i[p] = idx;
    }
}

// Merged kernel: first TOPK_BLOCKS do rank-by-count top-k; the rest do LOI.
// The last topk block to finish resets g_cnt/g_done so the next graph replay
// (and the next call) starts from zeroed counters without a reset kernel.
__global__ void __launch_bounds__(256) k_main(
    float* __restrict__ out,
    const float* __restrict__ md, const float* __restrict__ dis,
    const float* __restrict__ res, const float* __restrict__ joff,
    const int* __restrict__ topk)
{
    int lane = threadIdx.x & 31;

    if (blockIdx.x < TOPK_BLOCKS) {
        // ---- top-k: warp-per-candidate, stable (v desc, idx asc) ----
        int K = topk[0];
        int M = g_cnt[0];
        int Z = g_cnt[1];
        float* junc = out + (size_t)LOI_ELEMS;
        float* sc   = junc + 2*(size_t)K;
        int i = (blockIdx.x * blockDim.x + threadIdx.x) >> 5;

        if (i < M) {
            float v = g_cand_v[i];
            int  id = g_cand_i[i];
            int rank = 0;
            for (int j = lane; j < M; j += 32) {
                float vj = g_cand_v[j];
                int   ij = g_cand_i[j];
                rank += (int)((vj > v) | ((vj == v) & (ij < id)));
            }
            #pragma unroll
            for (int o = 16; o; o >>= 1) rank += __shfl_xor_sync(0xffffffffu, rank, o);
            if (lane == 0 && rank < K) {
                __stcs(&sc[rank], v);
                __stcs(&junc[2*rank+0], (float)(id & (WW-1)) + joff[id]        + 0.5f);
                __stcs(&junc[2*rank+1], (float)(id >> 7)     + joff[NPIX + id] + 0.5f);
            }
        }
        if (M < K && i < Z) {
            int zid = g_zero_i[i];
            int zr = 0;
            for (int j = lane; j < Z; j += 32)
                zr += (int)(g_zero_i[j] < zid);
            #pragma unroll
            for (int o = 16; o; o >>= 1) zr += __shfl_xor_sync(0xffffffffu, zr, o);
            int rk = M + zr;
            if (lane == 0 && rk < K) {
                __stcs(&sc[rk], 0.0f);
                __stcs(&junc[2*rk+0], (float)(zid & (WW-1)) + joff[zid]        + 0.5f);
                __stcs(&junc[2*rk+1], (float)(zid >> 7)     + joff[NPIX + zid] + 0.5f);
            }
        }

        // ---- deferred counter reset (replaces the k_reset kernel) ----
        __syncthreads();                       // all reads of g_cnt in this block done
        if (threadIdx.x == 0) {
            __threadfence();
            int d = atomicAdd(&g_done, 1);
            if (d == TOPK_BLOCKS - 1) {        // last topk block: all reads complete
                g_cnt[0] = 0;
                g_cnt[1] = 0;
                g_done   = 0;
                __threadfence();
            }
        }
        return;
    }

    // ---- LOI: one warp per line; hafm decoded in-warp (broadcast loads) ----
    int line = ((blockIdx.x - TOPK_BLOCKS) * blockDim.x + threadIdx.x) >> 5;
    int pix = line & (NPIX-1);
    int r   = line >> 14;               // residual index 0..4
    int x = pix & (WW-1), y = pix >> 7;

    const float PI = 3.14159265358979323846f;
    float md0 = md[pix], md1 = md[NPIX+pix], md2 = md[2*NPIX+pix];
    float d0 = dis[pix], r0 = res[pix];
    float md_un = (md0 - 0.5f) * (2.0f * PI);
    float cs  = cosf(md_un);
    float ss  = sinf(md_un);
    float yst = tanf(md1 * (PI * 0.5f));
    float yed = tanf(-md2 * (PI * 0.5f));
    float dist = fminf(fmaxf(d0 + r0*(float)(r-2), 0.0f), 1.0f) * SCALE;
    float fx = (float)x, fy = (float)y;
    float4 L;
    L.x = fminf(fmaxf((cs - ss*yst)*dist + fx, 0.0f), (float)(WW-1));
    L.y = fminf(fmaxf((ss + cs*yst)*dist + fy, 0.0f), (float)(HH-1));
    L.z = fminf(fmaxf((cs - ss*yed)*dist + fx, 0.0f), (float)(WW-1));
    L.w = fminf(fmaxf((ss + cs*yed)*dist + fy, 0.0f), (float)(HH-1));

    int c2 = lane >> 4;          // channel group: 0 or 1 (8 channels each)
    int tg = lane & 15;          // t-pair group: t = 2*tg + k

    const __half* fb = g_tfeat + c2*8;
    float2 acc[2][4];

    #pragma unroll
    for (int k = 0; k < 2; ++k) {
        float tf = (float)(2*tg + k) * (1.0f / 31.0f);
        float px = L.x*tf + L.z*(1.0f - tf) - 0.5f;
        float py = L.y*tf + L.w*(1.0f - tf) - 0.5f;

        float px0 = fminf(fmaxf(floorf(px), 0.0f), (float)(WW-1));
        float py0 = fminf(fmaxf(floorf(py), 0.0f), (float)(HH-1));
        float px1 = fminf(px0 + 1.0f, (float)(WW-1));
        float py1 = fminf(py0 + 1.0f, (float)(HH-1));
        float wx0 = px1 - px, wx1 = px - px0;
        float wy0 = py1 - py, wy1 = py - py0;
        float w00 = wy0*wx0, w10 = wy1*wx0, w01 = wy0*wx1, w11 = wy1*wx1;
        int ix0 = (int)px0, iy0 = (int)py0, ix1 = (int)px1, iy1 = (int)py1;

        uint4 q00 = *(const uint4*)(fb + (iy0*WW + ix0)*CC);
        uint4 q10 = *(const uint4*)(fb + (iy1*WW + ix0)*CC);
        uint4 q01 = *(const uint4*)(fb + (iy0*WW + ix1)*CC);
        uint4 q11 = *(const uint4*)(fb + (iy1*WW + ix1)*CC);

        const unsigned* u00 = (const unsigned*)&q00;
        const unsigned* u10 = (const unsigned*)&q10;
        const unsigned* u01 = (const unsigned*)&q01;
        const unsigned* u11 = (const unsigned*)&q11;

        #pragma unroll
        for (int p = 0; p < 4; ++p) {
            float2 a = __half22float2(*(const __half2*)&u00[p]);
            float2 b = __half22float2(*(const __half2*)&u10[p]);
            float2 c = __half22float2(*(const __half2*)&u01[p]);
            float2 d = __half22float2(*(const __half2*)&u11[p]);
            acc[k][p].x = a.x*w00 + b.x*w10 + c.x*w01 + d.x*w11;
            acc[k][p].y = a.y*w00 + b.y*w10 + c.y*w01 + d.y*w11;
        }
    }

    // streaming stores: out is write-only, keep it out of L2
    float* row = out + (size_t)line * (CC*NPTS) + c2*(8*NPTS) + 2*tg;
    #pragma unroll
    for (int p = 0; p < 4; ++p) {
        __stcs((float2*)(row + (2*p  )*NPTS), make_float2(acc[0][p].x, acc[1][p].x));
        __stcs((float2*)(row + (2*p+1)*NPTS), make_float2(acc[0][p].y, acc[1][p].y));
    }
}

extern "C" void kernel_launch(void* const* d_in, const int* in_sizes, int n_in,
                              void* d_out, int out_size)
{
    const float* md   = (const float*)d_in[0];
    const float* dis  = (const float*)d_in[1];
    const float* res  = (const float*)d_in[2];
    const float* feat = (const float*)d_in[3];
    const float* jloc = (const float*)d_in[4];
    const float* joff = (const float*)d_in[5];
    const int*   topk = (const int*)d_in[6];
    float* out = (float*)d_out;

    k_prep<<<NPIX/256, 256>>>(feat, jloc);
    k_main<<<TOPK_BLOCKS + LOI_BLOCKS, 256>>>(out, md, dis, res, joff, topk);
}

// round 10
// speedup vs baseline: 11.4587x; 1.0576x over previous
#include <cuda_runtime.h>
#include <cuda_fp16.h>

#define HH 128
#define WW 128
#define CC 16
#define NPIX (HH*WW)
#define NRES 5
#define NLINES (NRES*NPIX)
#define NPTS 32
#define SCALE 5.0f
#define LOI_ELEMS (NLINES*CC*NPTS)
#define TOPK_BLOCKS (NPIX/8)        // 2048 blocks, 1 warp per candidate
#define LOI_BLOCKS  (NLINES/8)      // 10240 blocks, 1 warp per line

// scratch (no allocations allowed)
__device__ __half g_tfeat[NPIX*CC];      // 0.5 MB, channel-last fp16 features
__device__ float4 g_lparam[NPIX];        // 256 KB, per-pixel (ax_st,ay_st,ax_ed,ay_ed)
__device__ float  g_cand_v[NPIX];
__device__ int    g_cand_i[NPIX];
__device__ int    g_zero_i[NPIX];
__device__ int    g_cnt[2];              // zero-init; self-resetting (see k_main)
__device__ int    g_done;                // zero-init; self-resetting

// features->fp16 channel-last, per-pixel hafm direction params, NMS + compaction
__global__ void __launch_bounds__(256) k_prep(
    const float* __restrict__ feat, const float* __restrict__ jloc,
    const float* __restrict__ md)
{
    __shared__ float s[CC*257];
    int tid = threadIdx.x;
    int idx = blockIdx.x * 256 + tid;
    int x = idx & (WW-1), y = idx >> 7;

    #pragma unroll
    for (int c = 0; c < CC; ++c)
        s[c*257 + tid] = feat[c*NPIX + idx];
    __syncthreads();
    {
        unsigned r[8];
        #pragma unroll
        for (int j = 0; j < 8; ++j) {
            __half2 h = __floats2half2_rn(s[(2*j)*257 + tid], s[(2*j+1)*257 + tid]);
            r[j] = *(unsigned*)&h;
        }
        uint4* dst = (uint4*)&g_tfeat[idx*CC];
        dst[0] = make_uint4(r[0], r[1], r[2], r[3]);
        dst[1] = make_uint4(r[4], r[5], r[6], r[7]);
    }

    // per-pixel hafm direction params (shared by all 5 residual lines)
    {
        const float PI = 3.14159265358979323846f;
        float md0 = md[idx], md1 = md[NPIX+idx], md2 = md[2*NPIX+idx];
        float md_un = (md0 - 0.5f) * (2.0f * PI);
        float cs  = cosf(md_un);
        float ss  = sinf(md_un);
        float yst = tanf(md1 * (PI * 0.5f));
        float yed = tanf(-md2 * (PI * 0.5f));
        g_lparam[idx] = make_float4(cs - ss*yst, ss + cs*yst,
                                    cs - ss*yed, ss + cs*yed);
    }

    float a = jloc[idx];
    float m = -1e30f;
    #pragma unroll
    for (int dy = -1; dy <= 1; ++dy) {
        int yy = y + dy;
        if (yy < 0 || yy >= HH) continue;
        #pragma unroll
        for (int dx = -1; dx <= 1; ++dx) {
            int xx = x + dx;
            if (xx < 0 || xx >= WW) continue;
            m = fmaxf(m, jloc[yy*WW + xx]);
        }
    }
    float v = (a == m) ? a : 0.0f;
    if (v > 0.0f) {
        int p = atomicAdd(&g_cnt[0], 1);
        g_cand_v[p] = v;
        g_cand_i[p] = idx;
    } else {
        int p = atomicAdd(&g_cnt[1], 1);
        g_zero_i[p] = idx;
    }
}

// Merged kernel: first TOPK_BLOCKS do rank-by-count top-k; the rest do LOI.
__global__ void __launch_bounds__(256) k_main(
    float* __restrict__ out,
    const float* __restrict__ dis, const float* __restrict__ res,
    const float* __restrict__ joff, const int* __restrict__ topk)
{
    int lane = threadIdx.x & 31;

    if (blockIdx.x < TOPK_BLOCKS) {
        // ---- top-k: warp-per-candidate, stable (v desc, idx asc) ----
        int K = topk[0];
        int M = g_cnt[0];
        int Z = g_cnt[1];
        float* junc = out + (size_t)LOI_ELEMS;
        float* sc   = junc + 2*(size_t)K;
        int i = (blockIdx.x * blockDim.x + threadIdx.x) >> 5;

        if (i < M) {
            float v = g_cand_v[i];
            int  id = g_cand_i[i];
            int rank = 0;
            for (int j = lane; j < M; j += 32) {
                float vj = g_cand_v[j];
                int   ij = g_cand_i[j];
                rank += (int)((vj > v) | ((vj == v) & (ij < id)));
            }
            #pragma unroll
            for (int o = 16; o; o >>= 1) rank += __shfl_xor_sync(0xffffffffu, rank, o);
            if (lane == 0 && rank < K) {
                __stcs(&sc[rank], v);
                __stcs(&junc[2*rank+0], (float)(id & (WW-1)) + joff[id]        + 0.5f);
                __stcs(&junc[2*rank+1], (float)(id >> 7)     + joff[NPIX + id] + 0.5f);
            }
        }
        if (M < K && i < Z) {
            int zid = g_zero_i[i];
            int zr = 0;
            for (int j = lane; j < Z; j += 32)
                zr += (int)(g_zero_i[j] < zid);
            #pragma unroll
            for (int o = 16; o; o >>= 1) zr += __shfl_xor_sync(0xffffffffu, zr, o);
            int rk = M + zr;
            if (lane == 0 && rk < K) {
                __stcs(&sc[rk], 0.0f);
                __stcs(&junc[2*rk+0], (float)(zid & (WW-1)) + joff[zid]        + 0.5f);
                __stcs(&junc[2*rk+1], (float)(zid >> 7)     + joff[NPIX + zid] + 0.5f);
            }
        }

        // ---- deferred counter reset (replaces a reset kernel) ----
        __syncthreads();
        if (threadIdx.x == 0) {
            __threadfence();
            int d = atomicAdd(&g_done, 1);
            if (d == TOPK_BLOCKS - 1) {
                g_cnt[0] = 0;
                g_cnt[1] = 0;
                g_done   = 0;
                __threadfence();
            }
        }
        return;
    }

    // ---- LOI: one warp per line; params from precomputed per-pixel table ----
    int line = ((blockIdx.x - TOPK_BLOCKS) * blockDim.x + threadIdx.x) >> 5;
    int pix = line & (NPIX-1);
    int r   = line >> 14;               // residual index 0..4
    int x = pix & (WW-1), y = pix >> 7;

    float4 A = g_lparam[pix];           // warp-broadcast LDG.128
    float dist = fminf(fmaxf(dis[pix] + res[pix]*(float)(r-2), 0.0f), 1.0f) * SCALE;
    float fx = (float)x, fy = (float)y;
    float4 L;
    L.x = fminf(fmaxf(A.x*dist + fx, 0.0f), (float)(WW-1));
    L.y = fminf(fmaxf(A.y*dist + fy, 0.0f), (float)(HH-1));
    L.z = fminf(fmaxf(A.z*dist + fx, 0.0f), (float)(WW-1));
    L.w = fminf(fmaxf(A.w*dist + fy, 0.0f), (float)(HH-1));

    int c2 = lane >> 4;          // channel group: 0 or 1 (8 channels each)
    int tg = lane & 15;          // t-pair group: t = 2*tg + k

    const __half* fb = g_tfeat + c2*8;
    float2 acc[2][4];

    #pragma unroll
    for (int k = 0; k < 2; ++k) {
        float tf = (float)(2*tg + k) * (1.0f / 31.0f);
        float px = L.x*tf + L.z*(1.0f - tf) - 0.5f;
        float py = L.y*tf + L.w*(1.0f - tf) - 0.5f;

        float px0 = fminf(fmaxf(floorf(px), 0.0f), (float)(WW-1));
        float py0 = fminf(fmaxf(floorf(py), 0.0f), (float)(HH-1));
        float px1 = fminf(px0 + 1.0f, (float)(WW-1));
        float py1 = fminf(py0 + 1.0f, (float)(HH-1));
        float wx0 = px1 - px, wx1 = px - px0;
        float wy0 = py1 - py, wy1 = py - py0;
        __half2 h00 = __float2half2_rn(wy0*wx0);
        __half2 h10 = __float2half2_rn(wy1*wx0);
        __half2 h01 = __float2half2_rn(wy0*wx1);
        __half2 h11 = __float2half2_rn(wy1*wx1);
        int ix0 = (int)px0, iy0 = (int)py0, ix1 = (int)px1, iy1 = (int)py1;

        uint4 q00 = *(const uint4*)(fb + (iy0*WW + ix0)*CC);
        uint4 q10 = *(const uint4*)(fb + (iy1*WW + ix0)*CC);
        uint4 q01 = *(const uint4*)(fb + (iy0*WW + ix1)*CC);
        uint4 q11 = *(const uint4*)(fb + (iy1*WW + ix1)*CC);

        const __half2* a00 = (const __half2*)&q00;
        const __half2* a10 = (const __half2*)&q10;
        const __half2* a01 = (const __half2*)&q01;
        const __half2* a11 = (const __half2*)&q11;

        #pragma unroll
        for (int p = 0; p < 4; ++p) {
            __half2 s = __hmul2(a00[p], h00);
            s = __hfma2(a10[p], h10, s);
            s = __hfma2(a01[p], h01, s);
            s = __hfma2(a11[p], h11, s);
            acc[k][p] = __half22float2(s);
        }
    }

    // streaming stores: out is write-only, keep it out of L2
    float* row = out + (size_t)line * (CC*NPTS) + c2*(8*NPTS) + 2*tg;
    #pragma unroll
    for (int p = 0; p < 4; ++p) {
        __stcs((float2*)(row + (2*p  )*NPTS), make_float2(acc[0][p].x, acc[1][p].x));
        __stcs((float2*)(row + (2*p+1)*NPTS), make_float2(acc[0][p].y, acc[1][p].y));
    }
}

extern "C" void kernel_launch(void* const* d_in, const int* in_sizes, int n_in,
                              void* d_out, int out_size)
{
    const float* md   = (const float*)d_in[0];
    const float* dis  = (const float*)d_in[1];
    const float* res  = (const float*)d_in[2];
    const float* feat = (const float*)d_in[3];
    const float* jloc = (const float*)d_in[4];
    const float* joff = (const float*)d_in[5];
    const int*   topk = (const int*)d_in[6];
    float* out = (float*)d_out;

    k_prep<<<NPIX/256, 256>>>(feat, jloc, md);
    k_main<<<TOPK_BLOCKS + LOI_BLOCKS, 256>>>(out, dis, res, joff, topk);
}

// round 13
// speedup vs baseline: 12.1776x; 1.0627x over previous
#include <cuda_runtime.h>
#include <cuda_fp16.h>

#define HH 128
#define WW 128
#define CC 16
#define NPIX (HH*WW)
#define NRES 5
#define NLINES (NRES*NPIX)
#define NPTS 32
#define SCALE 5.0f
#define LOI_ELEMS (NLINES*CC*NPTS)
#define TOPK_BLOCKS (NPIX/8)        // 2048 blocks, 1 warp per candidate
#define LOI_BLOCKS  (NLINES/8)      // 10240 blocks, 1 warp per line

// scratch (no allocations allowed)
// g_tfeat layout: 2x2-pixel quads, 64 halfs (128B) per quad:
//   addr_half = ((y>>1)*64 + (x>>1))*64 + (y&1)*32 + (x&1)*16 + c
__device__ __half g_tfeat[NPIX*CC];      // 0.5 MB
__device__ float4 g_lparam[NPIX];        // 256 KB, per-pixel (ax_st,ay_st,ax_ed,ay_ed)
__device__ float  g_cand_v[NPIX];
__device__ int    g_cand_i[NPIX];
__device__ int    g_zero_i[NPIX];
__device__ int    g_cnt[2];              // zero-init; self-resetting (see k_main)
__device__ int    g_done;                // zero-init; self-resetting

// features->fp16 quad-tiled, per-pixel hafm direction params, NMS + compaction
__global__ void __launch_bounds__(256) k_prep(
    const float* __restrict__ feat, const float* __restrict__ jloc,
    const float* __restrict__ md)
{
    __shared__ float s[CC*257];
    int tid = threadIdx.x;
    int idx = blockIdx.x * 256 + tid;
    int x = idx & (WW-1), y = idx >> 7;

    #pragma unroll
    for (int c = 0; c < CC; ++c)
        s[c*257 + tid] = feat[c*NPIX + idx];
    __syncthreads();
    {
        unsigned r[8];
        #pragma unroll
        for (int j = 0; j < 8; ++j) {
            __half2 h = __floats2half2_rn(s[(2*j)*257 + tid], s[(2*j+1)*257 + tid]);
            r[j] = *(unsigned*)&h;
        }
        // quad-tiled destination (block covers 2 full rows -> whole quads)
        __half* dp = g_tfeat + (((y>>1)*(WW/2) + (x>>1))<<6)
                             + ((y&1)<<5) + ((x&1)<<4);
        ((uint4*)dp)[0] = make_uint4(r[0], r[1], r[2], r[3]);
        ((uint4*)dp)[1] = make_uint4(r[4], r[5], r[6], r[7]);
    }

    // per-pixel hafm direction params (shared by all 5 residual lines)
    {
        const float PI = 3.14159265358979323846f;
        float md0 = md[idx], md1 = md[NPIX+idx], md2 = md[2*NPIX+idx];
        float md_un = (md0 - 0.5f) * (2.0f * PI);
        float cs  = cosf(md_un);
        float ss  = sinf(md_un);
        float yst = tanf(md1 * (PI * 0.5f));
        float yed = tanf(-md2 * (PI * 0.5f));
        g_lparam[idx] = make_float4(cs - ss*yst, ss + cs*yst,
                                    cs - ss*yed, ss + cs*yed);
    }

    float a = jloc[idx];
    float m = -1e30f;
    #pragma unroll
    for (int dy = -1; dy <= 1; ++dy) {
        int yy = y + dy;
        if (yy < 0 || yy >= HH) continue;
        #pragma unroll
        for (int dx = -1; dx <= 1; ++dx) {
            int xx = x + dx;
            if (xx < 0 || xx >= WW) continue;
            m = fmaxf(m, jloc[yy*WW + xx]);
        }
    }
    float v = (a == m) ? a : 0.0f;
    if (v > 0.0f) {
        int p = atomicAdd(&g_cnt[0], 1);
        g_cand_v[p] = v;
        g_cand_i[p] = idx;
    } else {
        int p = atomicAdd(&g_cnt[1], 1);
        g_zero_i[p] = idx;
    }
}

__device__ __forceinline__ const uint4* tf_quad(int ix, int iy, int coff)
{
    return (const uint4*)(g_tfeat + (((iy>>1)*(WW/2) + (ix>>1))<<6)
                                  + ((iy&1)<<5) + ((ix&1)<<4) + coff);
}

// Merged kernel: first TOPK_BLOCKS do rank-by-count top-k; the rest do LOI.
__global__ void __launch_bounds__(256, 6) k_main(
    float* __restrict__ out,
    const float* __restrict__ dis, const float* __restrict__ res,
    const float* __restrict__ joff, const int* __restrict__ topk)
{
    int lane = threadIdx.x & 31;

    if (blockIdx.x < TOPK_BLOCKS) {
        // ---- top-k: warp-per-candidate, stable (v desc, idx asc) ----
        int K = topk[0];
        int M = g_cnt[0];
        int Z = g_cnt[1];
        float* junc = out + (size_t)LOI_ELEMS;
        float* sc   = junc + 2*(size_t)K;
        int i = (blockIdx.x * blockDim.x + threadIdx.x) >> 5;

        if (i < M) {
            float v = g_cand_v[i];
            int  id = g_cand_i[i];
            int rank = 0;
            for (int j = lane; j < M; j += 32) {
                float vj = g_cand_v[j];
                int   ij = g_cand_i[j];
                rank += (int)((vj > v) | ((vj == v) & (ij < id)));
            }
            #pragma unroll
            for (int o = 16; o; o >>= 1) rank += __shfl_xor_sync(0xffffffffu, rank, o);
            if (lane == 0 && rank < K) {
                __stcs(&sc[rank], v);
                __stcs(&junc[2*rank+0], (float)(id & (WW-1)) + joff[id]        + 0.5f);
                __stcs(&junc[2*rank+1], (float)(id >> 7)     + joff[NPIX + id] + 0.5f);
            }
        }
        if (M < K && i < Z) {
            int zid = g_zero_i[i];
            int zr = 0;
            for (int j = lane; j < Z; j += 32)
                zr += (int)(g_zero_i[j] < zid);
            #pragma unroll
            for (int o = 16; o; o >>= 1) zr += __shfl_xor_sync(0xffffffffu, zr, o);
            int rk = M + zr;
            if (lane == 0 && rk < K) {
                __stcs(&sc[rk], 0.0f);
                __stcs(&junc[2*rk+0], (float)(zid & (WW-1)) + joff[zid]        + 0.5f);
                __stcs(&junc[2*rk+1], (float)(zid >> 7)     + joff[NPIX + zid] + 0.5f);
            }
        }

        // ---- deferred counter reset (replaces a reset kernel) ----
        __syncthreads();
        if (threadIdx.x == 0) {
            __threadfence();
            int d = atomicAdd(&g_done, 1);
            if (d == TOPK_BLOCKS - 1) {
                g_cnt[0] = 0;
                g_cnt[1] = 0;
                g_done   = 0;
                __threadfence();
            }
        }
        return;
    }

    // ---- LOI: one warp per line; params from precomputed per-pixel table ----
    int line = ((blockIdx.x - TOPK_BLOCKS) * blockDim.x + threadIdx.x) >> 5;
    int pix = line & (NPIX-1);
    int r   = line >> 14;               // residual index 0..4
    int x = pix & (WW-1), y = pix >> 7;

    float4 A = g_lparam[pix];           // warp-broadcast LDG.128
    float dist = fminf(fmaxf(dis[pix] + res[pix]*(float)(r-2), 0.0f), 1.0f) * SCALE;
    float fx = (float)x, fy = (float)y;
    float4 L;
    L.x = fminf(fmaxf(A.x*dist + fx, 0.0f), (float)(WW-1));
    L.y = fminf(fmaxf(A.y*dist + fy, 0.0f), (float)(HH-1));
    L.z = fminf(fmaxf(A.z*dist + fx, 0.0f), (float)(WW-1));
    L.w = fminf(fmaxf(A.w*dist + fy, 0.0f), (float)(HH-1));

    int c2 = lane >> 4;          // channel group: 0 or 1 (8 channels each)
    int tg = lane & 15;          // t-pair group: t = 2*tg + k
    int coff = c2 << 3;          // half-offset of this channel half in a quad slot

    float2 acc[2][4];

    #pragma unroll
    for (int k = 0; k < 2; ++k) {
        float tf = (float)(2*tg + k) * (1.0f / 31.0f);
        float px = L.x*tf + L.z*(1.0f - tf) - 0.5f;
        float py = L.y*tf + L.w*(1.0f - tf) - 0.5f;

        float px0 = fminf(fmaxf(floorf(px), 0.0f), (float)(WW-1));
        float py0 = fminf(fmaxf(floorf(py), 0.0f), (float)(HH-1));
        float px1 = fminf(px0 + 1.0f, (float)(WW-1));
        float py1 = fminf(py0 + 1.0f, (float)(HH-1));
        float wx0 = px1 - px, wx1 = px - px0;
        float wy0 = py1 - py, wy1 = py - py0;
        __half2 h00 = __float2half2_rn(wy0*wx0);
        __half2 h10 = __float2half2_rn(wy1*wx0);
        __half2 h01 = __float2half2_rn(wy0*wx1);
        __half2 h11 = __float2half2_rn(wy1*wx1);
        int ix0 = (int)px0, iy0 = (int)py0, ix1 = (int)px1, iy1 = (int)py1;

        uint4 q00 = *tf_quad(ix0, iy0, coff);
        uint4 q10 = *tf_quad(ix0, iy1, coff);
        uint4 q01 = *tf_quad(ix1, iy0, coff);
        uint4 q11 = *tf_quad(ix1, iy1, coff);

        const __half2* a00 = (const __half2*)&q00;
        const __half2* a10 = (const __half2*)&q10;
        const __half2* a01 = (const __half2*)&q01;
        const __half2* a11 = (const __half2*)&q11;

        #pragma unroll
        for (int p = 0; p < 4; ++p) {
            __half2 s = __hmul2(a00[p], h00);
            s = __hfma2(a10[p], h10, s);
            s = __hfma2(a01[p], h01, s);
            s = __hfma2(a11[p], h11, s);
            acc[k][p] = __half22float2(s);
        }
    }

    // streaming stores: out is write-only, keep it out of L2
    float* row = out + (size_t)line * (CC*NPTS) + c2*(8*NPTS) + 2*tg;
    #pragma unroll
    for (int p = 0; p < 4; ++p) {
        __stcs((float2*)(row + (2*p  )*NPTS), make_float2(acc[0][p].x, acc[1][p].x));
        __stcs((float2*)(row + (2*p+1)*NPTS), make_float2(acc[0][p].y, acc[1][p].y));
    }
}

extern "C" void kernel_launch(void* const* d_in, const int* in_sizes, int n_in,
                              void* d_out, int out_size)
{
    const float* md   = (const float*)d_in[0];
    const float* dis  = (const float*)d_in[1];
    const float* res  = (const float*)d_in[2];
    const float* feat = (const float*)d_in[3];
    const float* jloc = (const float*)d_in[4];
    const float* joff = (const float*)d_in[5];
    const int*   topk = (const int*)d_in[6];
    float* out = (float*)d_out;

    k_prep<<<NPIX/256, 256>>>(feat, jloc, md);
    k_main<<<TOPK_BLOCKS + LOI_BLOCKS, 256>>>(out, dis, res, joff, topk);
}